// round 12
// baseline (speedup 1.0000x reference)
#include <cuda_runtime.h>
#include <cstdint>

#define GRID_C 148

__device__ float G1d[2097152]; // [8192][256] = 1 - h1^2
__device__ float G2d[2097152]; // [8192][256] = 1 - h2^2
__device__ float W2P[65536];   // frag-permuted tf32 W2 (L2-resident B)
__device__ float W1P[16384];   // frag-permuted tf32 W1
__device__ float W3P[16384];   // frag-permuted tf32 W3^T (A-side)

typedef unsigned long long u64;
__device__ __forceinline__ float rnaf(float f){
    uint32_t o; asm("cvt.rna.tf32.f32 %0, %1;" : "=r"(o) : "f"(f)); return __uint_as_float(o);
}
__device__ __forceinline__ u64 pk2(float s){ u64 r; asm("mov.b64 %0,{%1,%1};" : "=l"(r) : "f"(s)); return r; }
__device__ __forceinline__ u64 fma2(u64 a, u64 b, u64 c){ u64 d; asm("fma.rn.f32x2 %0,%1,%2,%3;" : "=l"(d) : "l"(a), "l"(b), "l"(c)); return d; }
__device__ __forceinline__ void mma8(float* c, const uint32_t* a, const uint32_t* b){
    asm volatile("mma.sync.aligned.m16n8k8.row.col.f32.tf32.tf32.f32 "
        "{%0,%1,%2,%3},{%4,%5,%6,%7},{%8,%9},{%0,%1,%2,%3};"
        : "+f"(c[0]), "+f"(c[1]), "+f"(c[2]), "+f"(c[3])
        : "r"(a[0]), "r"(a[1]), "r"(a[2]), "r"(a[3]), "r"(b[0]), "r"(b[1]));
}
#define CPA(dst, src) asm volatile("cp.async.cg.shared.global [%0],[%1],16;" :: "r"(dst), "l"(src) : "memory")
__device__ __forceinline__ uint32_t su32(const void* p){
    uint32_t a; asm("{.reg .u64 t; cvta.to.shared.u64 t,%1; cvt.u32.u64 %0,t;}" : "=r"(a) : "l"(p)); return a;
}
#define WGBAR(id) asm volatile("bar.sync %0, 256;" :: "r"(id) : "memory")

// ---------------- setup: prep (weight images) + fwd (exact g1/g2), one launch ----------------
__global__ void __launch_bounds__(256, 1) setup(const float* __restrict__ x,  const float* __restrict__ W1,
                                                const float* __restrict__ b1, const float* __restrict__ W2,
                                                const float* __restrict__ b2, const float* __restrict__ W3){
    // --- prep part (grid-stride) ---
    {
        int i = blockIdx.x * blockDim.x + threadIdx.x, stride = gridDim.x * blockDim.x;
        for (int idx = i; idx < 65536; idx += stride){
            int w = idx & 1, lane = (idx >> 1) & 31, ks = (idx >> 6) & 31, lt = (idx >> 11) & 3, c = idx >> 13;
            int l = c * 32 + lt * 8 + (lane >> 2), k = ks * 8 + (lane & 3) + 4 * w;
            W2P[idx] = rnaf(W2[l * 256 + k]);
        }
        for (int idx = i; idx < 16384; idx += stride){
            int w = idx & 1, lane = (idx >> 1) & 31, ksg = (idx >> 6) & 31, jt = idx >> 11;
            int j = jt * 8 + (lane >> 2), l = ksg * 8 + (lane & 3) + 4 * w;
            W1P[idx] = rnaf(W1[j * 256 + l]);
        }
        for (int idx = i; idx < 16384; idx += stride){
            int w = idx & 3, lane = (idx >> 2) & 31, ks = (idx >> 7) & 31, mt = idx >> 12;
            int m = mt * 16 + (lane >> 2) + 8 * (w & 1);
            int k = ks * 8 + (lane & 3) + 4 * (w >> 1);
            W3P[idx] = rnaf(W3[k * 64 + m]);
        }
    }
    // --- fwd part: block handles 64 batches ---
    extern __shared__ float fs[];
    float* xs  = fs;             // [64 j][66]
    float* h1t = fs + 64 * 66;   // [256 l][66]
    const int t = threadIdx.x;
    const int b0 = blockIdx.x * 64;
    for (int r = 0; r < 16; r++){
        int idx = r * 256 + t, b = idx >> 6, j = idx & 63;
        xs[j * 66 + b] = x[(size_t)(b0 + b) * 64 + j];
    }
    __syncthreads();
    u64 acc[32];
    #pragma unroll
    for (int q = 0; q < 32; q++) acc[q] = 0ull;
    for (int j = 0; j < 64; j++){
        u64 wp = pk2(W1[j * 256 + t]);
        const u64* xr = (const u64*)(xs + j * 66);
        #pragma unroll
        for (int q = 0; q < 32; q++) acc[q] = fma2(xr[q], wp, acc[q]);
    }
    float bb = b1[t];
    #pragma unroll
    for (int q = 0; q < 32; q++){
        float2 f; asm("mov.b64 {%0,%1},%2;" : "=f"(f.x), "=f"(f.y) : "l"(acc[q]));
        float ha = tanhf(f.x + bb), hb = tanhf(f.y + bb);
        h1t[t * 66 + 2*q] = ha; h1t[t * 66 + 2*q + 1] = hb;
        G1d[(size_t)(b0 + 2*q) * 256 + t]     = 1.f - ha * ha;
        G1d[(size_t)(b0 + 2*q + 1) * 256 + t] = 1.f - hb * hb;
    }
    __syncthreads();
    #pragma unroll
    for (int q = 0; q < 32; q++) acc[q] = 0ull;
    for (int l = 0; l < 256; l++){
        u64 wp = pk2(W2[l * 256 + t]);
        const u64* hr = (const u64*)(h1t + l * 66);
        #pragma unroll
        for (int q = 0; q < 32; q++) acc[q] = fma2(hr[q], wp, acc[q]);
    }
    bb = b2[t];
    #pragma unroll
    for (int q = 0; q < 32; q++){
        float2 f; asm("mov.b64 {%0,%1},%2;" : "=f"(f.x), "=f"(f.y) : "l"(acc[q]));
        float ha = tanhf(f.x + bb), hb = tanhf(f.y + bb);
        G2d[(size_t)(b0 + 2*q) * 256 + t]     = 1.f - ha * ha;
        G2d[(size_t)(b0 + 2*q + 1) * 256 + t] = 1.f - hb * hb;
    }
}

// ---------------- jmain: 512 thr, 2 batches/CTA, m32n32 passes, B via LDG ----------------
// smem floats: W3s 16384 | C1P 2x16384 | g2s 2x256
#define SMF (16384 + 32768 + 512)

__global__ void __launch_bounds__(512, 1) jmain(float* __restrict__ out){
    extern __shared__ float s[];
    float* W3s = s;                 // 16384
    float* C1P = s + 16384;         // 2 x 16384 (full A2 image per batch)
    float* g2s = C1P + 32768;       // 2 x 256

    const int t = threadIdx.x, lane = t & 31, wid = t >> 5;
    const int wg = wid >> 3, w8 = wid & 7;
    const int g = lane >> 2, tg = lane & 3;
    const int t2 = t & 255;

    float* C1w = C1P + wg * 16384;
    float* g2w = g2s + wg * 256;
    const uint32_t w3sb = su32(W3s);

    // resident W3P (A operand), loaded once
    #pragma unroll
    for (int i = 0; i < 8; i++){
        int u = t + i * 512;
        CPA(w3sb + (uint32_t)u * 16, (const char*)W3P + u * 16);
    }
    asm volatile("cp.async.commit_group;\ncp.async.wait_group 0;" ::: "memory");
    __syncthreads();

    const float4* Ap  = (const float4*)W3s + lane;
    const float4* A2b = (const float4*)C1w;
    const float2* Bp2 = (const float2*)W2P + (size_t)(w8 * 4) * 1024 + lane;
    const float2* B2p = (const float2*)W1P + (size_t)w8 * 1024 + lane;
    const int idxA = tg * 8 + g;

    for (int p = blockIdx.x; p < 4096; p += GRID_C){
        const int b = 2 * p + wg;
        g2w[t2] = G2d[(size_t)b * 256 + t2];
        WGBAR(1 + wg);   // g2 visible; all wg warps past prior GEMM2 (C1P safe to overwrite)

        // ---- GEMM1 in two m32 passes: warp strip l in [32*w8, 32*w8+32), full K=256 ----
        #pragma unroll
        for (int h = 0; h < 2; h++){
            float C1r[4][2][4];   // [f (n8 frag)][mh][q]  -- 32 regs
            #pragma unroll
            for (int f = 0; f < 4; f++)
                #pragma unroll
                for (int mh = 0; mh < 2; mh++)
                    #pragma unroll
                    for (int q = 0; q < 4; q++) C1r[f][mh][q] = 0.f;

            #pragma unroll 4
            for (int ks = 0; ks < 32; ks++){
                const float ga = g2w[ks * 8 + tg], gb = g2w[ks * 8 + tg + 4];
                float2 Bs[4];
                #pragma unroll
                for (int f = 0; f < 4; f++){
                    float2 Br = Bp2[(f * 32 + ks) * 32];
                    Bs[f].x = rnaf(Br.x * ga); Bs[f].y = rnaf(Br.y * gb);
                }
                #pragma unroll
                for (int mh = 0; mh < 2; mh++){
                    float4 A = Ap[((2 * h + mh) * 32 + ks) * 32];
                    #pragma unroll
                    for (int f = 0; f < 4; f++)
                        mma8(C1r[f][mh], (const uint32_t*)&A, (const uint32_t*)&Bs[f]);
                }
            }

            // ---- park this m-half: scale by g1, frag-permuted A2 image ----
            const float* g1b = G1d + (size_t)b * 256 + 32 * w8;
            #pragma unroll
            for (int f = 0; f < 4; f++){
                const float g1v0 = __ldg(g1b + 8 * f + 2 * tg);
                const float g1v1 = __ldg(g1b + 8 * f + 2 * tg + 1);
                const int ss = 4 * w8 + f;
                #pragma unroll
                for (int q = 0; q < 4; q++){
                    const int par = q & 1;
                    const int l7 = 2 * tg + par;
                    const int tgp = l7 & 3, kh = l7 >> 2;
                    const int wq = (q >> 1) + 2 * kh;
                    const float gv = par ? g1v1 : g1v0;
                    #pragma unroll
                    for (int mh = 0; mh < 2; mh++){
                        const int mt = 2 * h + mh;
                        C1w[((mt * 32 + ss) * 32 + tgp * 8 + g) * 4 + wq] = rnaf(C1r[f][mh][q] * gv);
                    }
                }
            }
        }
        WGBAR(1 + wg);

        // ---- GEMM2: J[m64, j8-strip] = A2 x W1, full K=256 ----
        float J[4][4];
        #pragma unroll
        for (int mt = 0; mt < 4; mt++)
            #pragma unroll
            for (int q = 0; q < 4; q++) J[mt][q] = 0.f;

        #pragma unroll 4
        for (int ss = 0; ss < 32; ss++){
            float2 B = B2p[ss * 32];
            #pragma unroll
            for (int mt = 0; mt < 4; mt++){
                float4 A = A2b[(mt * 32 + ss) * 32 + idxA];
                mma8(J[mt], (const uint32_t*)&A, (const uint32_t*)&B);
            }
        }

        // ---- epilogue: J -> out[b] ----
        {
            float* ob = out + (size_t)b * 4096;
            const int cc = w8 * 8 + 2 * tg;
            #pragma unroll
            for (int mt = 0; mt < 4; mt++){
                const int r0 = mt * 16 + g;
                *(float2*)(ob + (size_t)r0 * 64 + cc)       = make_float2(J[mt][0], J[mt][1]);
                *(float2*)(ob + (size_t)(r0 + 8) * 64 + cc) = make_float2(J[mt][2], J[mt][3]);
            }
        }
    }
}

extern "C" void kernel_launch(void* const* d_in, const int* in_sizes, int n_in,
                              void* d_out, int out_size)
{
    const float* x  = (const float*)d_in[0];
    const float* W1 = (const float*)d_in[1];
    const float* b1 = (const float*)d_in[2];
    const float* W2 = (const float*)d_in[3];
    const float* b2 = (const float*)d_in[4];
    const float* W3 = (const float*)d_in[5];
    float* out = (float*)d_out;

    cudaFuncSetAttribute(setup, cudaFuncAttributeMaxDynamicSharedMemorySize, (64*66 + 256*66) * 4);
    cudaFuncSetAttribute(jmain, cudaFuncAttributeMaxDynamicSharedMemorySize, SMF * 4);

    setup<<<128, 256, (64*66 + 256*66) * 4>>>(x, W1, b1, W2, b2, W3);
    jmain<<<GRID_C, 512, SMF * 4>>>(out);
}

// round 14
// speedup vs baseline: 1.2781x; 1.2781x over previous
#include <cuda_runtime.h>
#include <cstdint>

#define GRID_C 148

__device__ float G1d[2097152]; // [8192][256] = 1 - h1^2
__device__ float G2d[2097152]; // [8192][256] = 1 - h2^2
__device__ float W2P[65536];   // frag-permuted tf32 W2 (L2-resident B)
__device__ float W1P[16384];   // frag-permuted tf32 W1
__device__ float W3P[16384];   // frag-permuted tf32 W3^T (A-side)

typedef unsigned long long u64;
__device__ __forceinline__ float rnaf(float f){
    uint32_t o; asm("cvt.rna.tf32.f32 %0, %1;" : "=r"(o) : "f"(f)); return __uint_as_float(o);
}
__device__ __forceinline__ u64 pk2(float s){ u64 r; asm("mov.b64 %0,{%1,%1};" : "=l"(r) : "f"(s)); return r; }
__device__ __forceinline__ u64 fma2(u64 a, u64 b, u64 c){ u64 d; asm("fma.rn.f32x2 %0,%1,%2,%3;" : "=l"(d) : "l"(a), "l"(b), "l"(c)); return d; }
__device__ __forceinline__ void mma8(float* c, const uint32_t* a, const uint32_t* b){
    asm volatile("mma.sync.aligned.m16n8k8.row.col.f32.tf32.tf32.f32 "
        "{%0,%1,%2,%3},{%4,%5,%6,%7},{%8,%9},{%0,%1,%2,%3};"
        : "+f"(c[0]), "+f"(c[1]), "+f"(c[2]), "+f"(c[3])
        : "r"(a[0]), "r"(a[1]), "r"(a[2]), "r"(a[3]), "r"(b[0]), "r"(b[1]));
}
#define CPA(dst, src) asm volatile("cp.async.cg.shared.global [%0],[%1],16;" :: "r"(dst), "l"(src) : "memory")
__device__ __forceinline__ uint32_t su32(const void* p){
    uint32_t a; asm("{.reg .u64 t; cvta.to.shared.u64 t,%1; cvt.u32.u64 %0,t;}" : "=r"(a) : "l"(p)); return a;
}

// ---------------- setup: prep (weight images) + fwd (exact g1/g2), one launch ----------------
__global__ void __launch_bounds__(256, 1) setup(const float* __restrict__ x,  const float* __restrict__ W1,
                                                const float* __restrict__ b1, const float* __restrict__ W2,
                                                const float* __restrict__ b2, const float* __restrict__ W3){
    {
        int i = blockIdx.x * blockDim.x + threadIdx.x, stride = gridDim.x * blockDim.x;
        for (int idx = i; idx < 65536; idx += stride){
            int w = idx & 1, lane = (idx >> 1) & 31, ks = (idx >> 6) & 31, lt = (idx >> 11) & 3, c = idx >> 13;
            int l = c * 32 + lt * 8 + (lane >> 2), k = ks * 8 + (lane & 3) + 4 * w;
            W2P[idx] = rnaf(W2[l * 256 + k]);
        }
        for (int idx = i; idx < 16384; idx += stride){
            int w = idx & 1, lane = (idx >> 1) & 31, ksg = (idx >> 6) & 31, jt = idx >> 11;
            int j = jt * 8 + (lane >> 2), l = ksg * 8 + (lane & 3) + 4 * w;
            W1P[idx] = rnaf(W1[j * 256 + l]);
        }
        for (int idx = i; idx < 16384; idx += stride){
            int w = idx & 3, lane = (idx >> 2) & 31, ks = (idx >> 7) & 31, mt = idx >> 12;
            int m = mt * 16 + (lane >> 2) + 8 * (w & 1);
            int k = ks * 8 + (lane & 3) + 4 * (w >> 1);
            W3P[idx] = rnaf(W3[k * 64 + m]);
        }
    }
    extern __shared__ float fs[];
    float* xs  = fs;             // [64 j][66]
    float* h1t = fs + 64 * 66;   // [256 l][66]
    const int t = threadIdx.x;
    const int b0 = blockIdx.x * 64;
    for (int r = 0; r < 16; r++){
        int idx = r * 256 + t, b = idx >> 6, j = idx & 63;
        xs[j * 66 + b] = x[(size_t)(b0 + b) * 64 + j];
    }
    __syncthreads();
    u64 acc[32];
    #pragma unroll
    for (int q = 0; q < 32; q++) acc[q] = 0ull;
    for (int j = 0; j < 64; j++){
        u64 wp = pk2(W1[j * 256 + t]);
        const u64* xr = (const u64*)(xs + j * 66);
        #pragma unroll
        for (int q = 0; q < 32; q++) acc[q] = fma2(xr[q], wp, acc[q]);
    }
    float bb = b1[t];
    #pragma unroll
    for (int q = 0; q < 32; q++){
        float2 f; asm("mov.b64 {%0,%1},%2;" : "=f"(f.x), "=f"(f.y) : "l"(acc[q]));
        float ha = tanhf(f.x + bb), hb = tanhf(f.y + bb);
        h1t[t * 66 + 2*q] = ha; h1t[t * 66 + 2*q + 1] = hb;
        G1d[(size_t)(b0 + 2*q) * 256 + t]     = 1.f - ha * ha;
        G1d[(size_t)(b0 + 2*q + 1) * 256 + t] = 1.f - hb * hb;
    }
    __syncthreads();
    #pragma unroll
    for (int q = 0; q < 32; q++) acc[q] = 0ull;
    for (int l = 0; l < 256; l++){
        u64 wp = pk2(W2[l * 256 + t]);
        const u64* hr = (const u64*)(h1t + l * 66);
        #pragma unroll
        for (int q = 0; q < 32; q++) acc[q] = fma2(hr[q], wp, acc[q]);
    }
    bb = b2[t];
    #pragma unroll
    for (int q = 0; q < 32; q++){
        float2 f; asm("mov.b64 {%0,%1},%2;" : "=f"(f.x), "=f"(f.y) : "l"(acc[q]));
        float ha = tanhf(f.x + bb), hb = tanhf(f.y + bb);
        G2d[(size_t)(b0 + 2*q) * 256 + t]     = 1.f - ha * ha;
        G2d[(size_t)(b0 + 2*q + 1) * 256 + t] = 1.f - hb * hb;
    }
}

// ---------------- jmain: 512 thr; ALL 16 warps share operand loads across the pair ----------------
// smem floats: W3s 16384 | C1P 2x16384 | g2s 2x512 (parity)
#define SMF (16384 + 32768 + 1024)

__global__ void __launch_bounds__(512, 1) jmain(float* __restrict__ out){
    extern __shared__ float s[];
    float* W3s = s;                 // 16384
    float* C1P = s + 16384;         // 2 x 16384 (per-batch A2 image)
    float* g2s = C1P + 32768;       // 2 x 512 (iteration-parity buffers)

    const int t = threadIdx.x, lane = t & 31, wid = t >> 5;
    const int g = lane >> 2, tg = lane & 3;
    const uint32_t w3sb = su32(W3s);

    // resident W3P (A operand), loaded once
    #pragma unroll
    for (int i = 0; i < 8; i++){
        int u = t + i * 512;
        CPA(w3sb + (uint32_t)u * 16, (const char*)W3P + u * 16);
    }
    asm volatile("cp.async.commit_group;\ncp.async.wait_group 0;" ::: "memory");
    __syncthreads();

    // GEMM1 pointers: warp owns n16 strip = n8-tiles {2*wid, 2*wid+1}
    const float4* Ap = (const float4*)W3s + lane;
    const int tt0 = 2 * wid, tt1 = tt0 + 1;
    const float2* Bq0 = (const float2*)W2P + (tt0 >> 2) * 4096 + (tt0 & 3) * 1024 + lane;
    const float2* Bq1 = (const float2*)W2P + (tt1 >> 2) * 4096 + (tt1 & 3) * 1024 + lane;

    // GEMM2: warp = (batch bg, m-half mh2, j16-strip jt16)
    const int bg = wid >> 3, u8 = wid & 7, jt16 = u8 & 3, mh2 = u8 >> 2;
    const float4* A2b = (const float4*)(C1P + bg * 16384);
    const float2* B20 = (const float2*)W1P + (2 * jt16) * 1024 + lane;
    const float2* B21 = (const float2*)W1P + (2 * jt16 + 1) * 1024 + lane;
    const int idxA = tg * 8 + g;

    int it = 0;
    for (int p = blockIdx.x; p < 4096; p += GRID_C, it ^= 1){
        float* g2c = g2s + it * 512;
        g2c[t] = G2d[(size_t)(2 * p + (t >> 8)) * 256 + (t & 255)];
        __syncthreads();   // g2 visible; all warps past prior GEMM2 (C1P safe)

        #pragma unroll
        for (int h = 0; h < 2; h++){
            float C1r[2][2][2][4];   // [b][f][mh][q] -- 32 regs
            #pragma unroll
            for (int b = 0; b < 2; b++)
                #pragma unroll
                for (int f = 0; f < 2; f++)
                    #pragma unroll
                    for (int mh = 0; mh < 2; mh++)
                        #pragma unroll
                        for (int q = 0; q < 4; q++) C1r[b][f][mh][q] = 0.f;

            #pragma unroll 4
            for (int ks = 0; ks < 32; ks++){
                float2 B0 = Bq0[ks * 32];
                float2 B1 = Bq1[ks * 32];
                float4 A0 = Ap[((2 * h + 0) * 32 + ks) * 32];
                float4 A1 = Ap[((2 * h + 1) * 32 + ks) * 32];
                #pragma unroll
                for (int b = 0; b < 2; b++){
                    const float ga = g2c[b * 256 + ks * 8 + tg];
                    const float gb = g2c[b * 256 + ks * 8 + tg + 4];
                    float2 S0, S1;
                    S0.x = rnaf(B0.x * ga); S0.y = rnaf(B0.y * gb);
                    S1.x = rnaf(B1.x * ga); S1.y = rnaf(B1.y * gb);
                    mma8(C1r[b][0][0], (const uint32_t*)&A0, (const uint32_t*)&S0);
                    mma8(C1r[b][0][1], (const uint32_t*)&A1, (const uint32_t*)&S0);
                    mma8(C1r[b][1][0], (const uint32_t*)&A0, (const uint32_t*)&S1);
                    mma8(C1r[b][1][1], (const uint32_t*)&A1, (const uint32_t*)&S1);
                }
            }

            // park both batches: scale by g1, frag-permuted A2 image
            #pragma unroll
            for (int b = 0; b < 2; b++){
                float* C1w = C1P + b * 16384;
                const float* g1b = G1d + (size_t)(2 * p + b) * 256 + 16 * wid;
                #pragma unroll
                for (int f = 0; f < 2; f++){
                    const float g1v0 = __ldg(g1b + 8 * f + 2 * tg);
                    const float g1v1 = __ldg(g1b + 8 * f + 2 * tg + 1);
                    const int ss = 2 * wid + f;
                    #pragma unroll
                    for (int q = 0; q < 4; q++){
                        const int par = q & 1;
                        const int l7 = 2 * tg + par;
                        const int tgp = l7 & 3, kh = l7 >> 2;
                        const int wq = (q >> 1) + 2 * kh;
                        const float gv = par ? g1v1 : g1v0;
                        #pragma unroll
                        for (int mh = 0; mh < 2; mh++){
                            const int mt = 2 * h + mh;
                            C1w[((mt * 32 + ss) * 32 + tgp * 8 + g) * 4 + wq] = rnaf(C1r[b][f][mh][q] * gv);
                        }
                    }
                }
            }
        }
        __syncthreads();

        // ---- GEMM2: warp tile m32 x n16, full K=256 ----
        float J[2][2][4];   // [f][mh]
        #pragma unroll
        for (int f = 0; f < 2; f++)
            #pragma unroll
            for (int mh = 0; mh < 2; mh++)
                #pragma unroll
                for (int q = 0; q < 4; q++) J[f][mh][q] = 0.f;

        #pragma unroll 4
        for (int ss = 0; ss < 32; ss++){
            float2 Bb0 = B20[ss * 32];
            float2 Bb1 = B21[ss * 32];
            #pragma unroll
            for (int mh = 0; mh < 2; mh++){
                const int mt = 2 * mh2 + mh;
                float4 A = A2b[(mt * 32 + ss) * 32 + idxA];
                mma8(J[0][mh], (const uint32_t*)&A, (const uint32_t*)&Bb0);
                mma8(J[1][mh], (const uint32_t*)&A, (const uint32_t*)&Bb1);
            }
        }

        // ---- epilogue ----
        {
            float* ob = out + (size_t)(2 * p + bg) * 4096;
            #pragma unroll
            for (int f = 0; f < 2; f++){
                const int cc = (2 * jt16 + f) * 8 + 2 * tg;
                #pragma unroll
                for (int mh = 0; mh < 2; mh++){
                    const int r0 = (2 * mh2 + mh) * 16 + g;
                    *(float2*)(ob + (size_t)r0 * 64 + cc)       = make_float2(J[f][mh][0], J[f][mh][1]);
                    *(float2*)(ob + (size_t)(r0 + 8) * 64 + cc) = make_float2(J[f][mh][2], J[f][mh][3]);
                }
            }
        }
    }
}

extern "C" void kernel_launch(void* const* d_in, const int* in_sizes, int n_in,
                              void* d_out, int out_size)
{
    const float* x  = (const float*)d_in[0];
    const float* W1 = (const float*)d_in[1];
    const float* b1 = (const float*)d_in[2];
    const float* W2 = (const float*)d_in[3];
    const float* b2 = (const float*)d_in[4];
    const float* W3 = (const float*)d_in[5];
    float* out = (float*)d_out;

    cudaFuncSetAttribute(setup, cudaFuncAttributeMaxDynamicSharedMemorySize, (64*66 + 256*66) * 4);
    cudaFuncSetAttribute(jmain, cudaFuncAttributeMaxDynamicSharedMemorySize, SMF * 4);

    setup<<<128, 256, (64*66 + 256*66) * 4>>>(x, W1, b1, W2, b2, W3);
    jmain<<<GRID_C, 512, SMF * 4>>>(out);
}

// round 15
// speedup vs baseline: 1.2924x; 1.0112x over previous
#include <cuda_runtime.h>
#include <cstdint>

#define GRID_C 148

__device__ float G1d[2097152]; // [8192][256] = 1 - h1^2
__device__ float G2d[2097152]; // [8192][256] = 1 - h2^2
__device__ float W2P[65536];   // frag-permuted tf32 W2, ks-paired: [tt32][ksg16][lane][4]
__device__ float W1P[16384];   // frag-permuted tf32 W1, ks-paired: [jt8][ksg16][lane][4]
__device__ float W3P[16384];   // frag-permuted tf32 W3^T (A-side): [mt4][ks32][lane][4]

typedef unsigned long long u64;
__device__ __forceinline__ float rnaf(float f){
    uint32_t o; asm("cvt.rna.tf32.f32 %0, %1;" : "=r"(o) : "f"(f)); return __uint_as_float(o);
}
__device__ __forceinline__ u64 pk2(float s){ u64 r; asm("mov.b64 %0,{%1,%1};" : "=l"(r) : "f"(s)); return r; }
__device__ __forceinline__ u64 fma2(u64 a, u64 b, u64 c){ u64 d; asm("fma.rn.f32x2 %0,%1,%2,%3;" : "=l"(d) : "l"(a), "l"(b), "l"(c)); return d; }
__device__ __forceinline__ void mma8(float* c, const uint32_t* a, const uint32_t* b){
    asm volatile("mma.sync.aligned.m16n8k8.row.col.f32.tf32.tf32.f32 "
        "{%0,%1,%2,%3},{%4,%5,%6,%7},{%8,%9},{%0,%1,%2,%3};"
        : "+f"(c[0]), "+f"(c[1]), "+f"(c[2]), "+f"(c[3])
        : "r"(a[0]), "r"(a[1]), "r"(a[2]), "r"(a[3]), "r"(b[0]), "r"(b[1]));
}
#define CPA(dst, src) asm volatile("cp.async.cg.shared.global [%0],[%1],16;" :: "r"(dst), "l"(src) : "memory")
__device__ __forceinline__ uint32_t su32(const void* p){
    uint32_t a; asm("{.reg .u64 t; cvta.to.shared.u64 t,%1; cvt.u32.u64 %0,t;}" : "=r"(a) : "l"(p)); return a;
}

// ---------------- setup: prep (weight images) + fwd (exact g1/g2), one launch ----------------
__global__ void __launch_bounds__(256, 1) setup(const float* __restrict__ x,  const float* __restrict__ W1,
                                                const float* __restrict__ b1, const float* __restrict__ W2,
                                                const float* __restrict__ b2, const float* __restrict__ W3){
    {
        int i = blockIdx.x * blockDim.x + threadIdx.x, stride = gridDim.x * blockDim.x;
        for (int idx = i; idx < 65536; idx += stride){
            int w = idx & 3, lane = (idx >> 2) & 31, ksg = (idx >> 7) & 15, tt = idx >> 11;
            int ks = 2 * ksg + (w >> 1), reg = w & 1;
            int l = tt * 8 + (lane >> 2), k = ks * 8 + (lane & 3) + 4 * reg;
            W2P[idx] = rnaf(W2[l * 256 + k]);
        }
        for (int idx = i; idx < 16384; idx += stride){
            int w = idx & 3, lane = (idx >> 2) & 31, ksg = (idx >> 7) & 15, jt = idx >> 11;
            int ks = 2 * ksg + (w >> 1), reg = w & 1;
            int j = jt * 8 + (lane >> 2), ll = ks * 8 + (lane & 3) + 4 * reg;
            W1P[idx] = rnaf(W1[j * 256 + ll]);
        }
        for (int idx = i; idx < 16384; idx += stride){
            int w = idx & 3, lane = (idx >> 2) & 31, ks = (idx >> 7) & 31, mt = idx >> 12;
            int m = mt * 16 + (lane >> 2) + 8 * (w & 1);
            int k = ks * 8 + (lane & 3) + 4 * (w >> 1);
            W3P[idx] = rnaf(W3[k * 64 + m]);
        }
    }
    extern __shared__ float fs[];
    float* xs  = fs;             // [64 j][66]
    float* h1t = fs + 64 * 66;   // [256 l][66]
    const int t = threadIdx.x;
    const int b0 = blockIdx.x * 64;
    for (int r = 0; r < 16; r++){
        int idx = r * 256 + t, b = idx >> 6, j = idx & 63;
        xs[j * 66 + b] = x[(size_t)(b0 + b) * 64 + j];
    }
    __syncthreads();
    u64 acc[32];
    #pragma unroll
    for (int q = 0; q < 32; q++) acc[q] = 0ull;
    for (int j = 0; j < 64; j++){
        u64 wp = pk2(W1[j * 256 + t]);
        const u64* xr = (const u64*)(xs + j * 66);
        #pragma unroll
        for (int q = 0; q < 32; q++) acc[q] = fma2(xr[q], wp, acc[q]);
    }
    float bb = b1[t];
    #pragma unroll
    for (int q = 0; q < 32; q++){
        float2 f; asm("mov.b64 {%0,%1},%2;" : "=f"(f.x), "=f"(f.y) : "l"(acc[q]));
        float ha = tanhf(f.x + bb), hb = tanhf(f.y + bb);
        h1t[t * 66 + 2*q] = ha; h1t[t * 66 + 2*q + 1] = hb;
        G1d[(size_t)(b0 + 2*q) * 256 + t]     = 1.f - ha * ha;
        G1d[(size_t)(b0 + 2*q + 1) * 256 + t] = 1.f - hb * hb;
    }
    __syncthreads();
    #pragma unroll
    for (int q = 0; q < 32; q++) acc[q] = 0ull;
    for (int l = 0; l < 256; l++){
        u64 wp = pk2(W2[l * 256 + t]);
        const u64* hr = (const u64*)(h1t + l * 66);
        #pragma unroll
        for (int q = 0; q < 32; q++) acc[q] = fma2(hr[q], wp, acc[q]);
    }
    bb = b2[t];
    #pragma unroll
    for (int q = 0; q < 32; q++){
        float2 f; asm("mov.b64 {%0,%1},%2;" : "=f"(f.x), "=f"(f.y) : "l"(acc[q]));
        float ha = tanhf(f.x + bb), hb = tanhf(f.y + bb);
        G2d[(size_t)(b0 + 2*q) * 256 + t]     = 1.f - ha * ha;
        G2d[(size_t)(b0 + 2*q + 1) * 256 + t] = 1.f - hb * hb;
    }
}

// ---------------- jmain: 512 thr, 4 batches/CTA, m-half pipelined ----------------
// smem floats: W3s 16384 | C1H 4x8192 | g2q 2x1024(parity)
#define SMF (16384 + 32768 + 2048)

__global__ void __launch_bounds__(512, 1) jmain(float* __restrict__ out){
    extern __shared__ float s[];
    float* W3s = s;                 // 16384
    float* C1H = s + 16384;         // 4 x 8192 (per-batch m32-half A2 image)
    float* g2q = C1H + 32768;       // 2 x 1024 (parity float4 quads)

    const int t = threadIdx.x, lane = t & 31, wid = t >> 5;
    const int g = lane >> 2, tg = lane & 3;
    const uint32_t w3sb = su32(W3s);

    // resident W3P (A operand), loaded once
    #pragma unroll
    for (int i = 0; i < 8; i++){
        int u = t + i * 512;
        CPA(w3sb + (uint32_t)u * 16, (const char*)W3P + u * 16);
    }
    asm volatile("cp.async.commit_group;\ncp.async.wait_group 0;" ::: "memory");
    __syncthreads();

    const float4* W3s4 = (const float4*)W3s;
    const float4* B1p  = (const float4*)W2P;
    const float4* B2p  = (const float4*)W1P;
    const float4* g2q4 = (const float4*)g2q;
    const int tt0 = 2 * wid, tt1 = tt0 + 1;

    // GEMM2 warp map: batch bq, m16 slot mq, n32 half nh
    const int bq = wid & 3, slot = wid >> 2, mq = slot & 1, nh = slot >> 1;
    const float4* A2b4 = (const float4*)(C1H + bq * 8192);
    const int idxA = tg * 8 + g;

    // park constants
    const int ca = (2 * tg) & 3, wa = 2 * ((2 * tg) >> 2);
    const int cb = (2 * tg + 1) & 3;

    int it = 0;
    for (int p = blockIdx.x; p < 2048; p += GRID_C, it ^= 1){
        // build g2 float4 quads for 4 batches
        if (t < 256){
            const int b = t >> 6, e = t & 63;
            const size_t base = (size_t)(4 * p + b) * 256 + 16 * (e >> 2) + (e & 3);
            float4 v;
            v.x = G2d[base]; v.y = G2d[base + 4]; v.z = G2d[base + 8]; v.w = G2d[base + 12];
            ((float4*)g2q)[it * 256 + b * 64 + e] = v;
        }
        __syncthreads();

        #pragma unroll
        for (int h2 = 0; h2 < 2; h2++){
            // ---- GEMM1: two m16 passes for this half ----
            #pragma unroll
            for (int ml = 0; ml < 2; ml++){
                const int mt = 2 * h2 + ml;
                float C1r[4][2][4];
                #pragma unroll
                for (int b = 0; b < 4; b++)
                    #pragma unroll
                    for (int f = 0; f < 2; f++)
                        #pragma unroll
                        for (int q = 0; q < 4; q++) C1r[b][f][q] = 0.f;

                #pragma unroll 4
                for (int ksg = 0; ksg < 16; ksg++){
                    float4 A0 = W3s4[(mt * 32 + 2 * ksg) * 32 + lane];
                    float4 A1 = W3s4[(mt * 32 + 2 * ksg + 1) * 32 + lane];
                    float4 Bf0 = B1p[(tt0 * 16 + ksg) * 32 + lane];
                    float4 Bf1 = B1p[(tt1 * 16 + ksg) * 32 + lane];
                    #pragma unroll
                    for (int b = 0; b < 4; b++){
                        float4 gq = g2q4[it * 256 + b * 64 + ksg * 4 + tg];
                        float2 S0, S1;
                        S0.x = rnaf(Bf0.x * gq.x); S0.y = rnaf(Bf0.y * gq.y);
                        S1.x = rnaf(Bf1.x * gq.x); S1.y = rnaf(Bf1.y * gq.y);
                        mma8(C1r[b][0], (const uint32_t*)&A0, (const uint32_t*)&S0);
                        mma8(C1r[b][1], (const uint32_t*)&A0, (const uint32_t*)&S1);
                        S0.x = rnaf(Bf0.z * gq.z); S0.y = rnaf(Bf0.w * gq.w);
                        S1.x = rnaf(Bf1.z * gq.z); S1.y = rnaf(Bf1.w * gq.w);
                        mma8(C1r[b][0], (const uint32_t*)&A1, (const uint32_t*)&S0);
                        mma8(C1r[b][1], (const uint32_t*)&A1, (const uint32_t*)&S1);
                    }
                }

                // ---- park this m16 into half-images (float2, g1-scaled, tf32) ----
                #pragma unroll
                for (int b = 0; b < 4; b++){
                    float* C1w = C1H + b * 8192;
                    const float* g1b = G1d + (size_t)(4 * p + b) * 256 + 16 * wid;
                    #pragma unroll
                    for (int f = 0; f < 2; f++){
                        const float gv0 = __ldg(g1b + 8 * f + 2 * tg);
                        const float gv1 = __ldg(g1b + 8 * f + 2 * tg + 1);
                        const int ss = 2 * wid + f;
                        float2 v0, v1;
                        v0.x = rnaf(C1r[b][f][0] * gv0); v0.y = rnaf(C1r[b][f][2] * gv0);
                        v1.x = rnaf(C1r[b][f][1] * gv1); v1.y = rnaf(C1r[b][f][3] * gv1);
                        *(float2*)&C1w[((ml * 32 + ss) * 32 + ca * 8 + g) * 4 + wa] = v0;
                        *(float2*)&C1w[((ml * 32 + ss) * 32 + cb * 8 + g) * 4 + wa] = v1;
                    }
                }
            }
            __syncthreads();   // half-images complete

            // ---- GEMM2 on this m-half: warp tile m16 x n32 ----
            float J[4][4];
            #pragma unroll
            for (int f = 0; f < 4; f++)
                #pragma unroll
                for (int q = 0; q < 4; q++) J[f][q] = 0.f;

            #pragma unroll 4
            for (int ksg = 0; ksg < 16; ksg++){
                float4 A0 = A2b4[(mq * 32 + 2 * ksg) * 32 + idxA];
                float4 A1 = A2b4[(mq * 32 + 2 * ksg + 1) * 32 + idxA];
                #pragma unroll
                for (int f = 0; f < 4; f++){
                    float4 Bv = B2p[((nh * 4 + f) * 16 + ksg) * 32 + lane];
                    float2 Be = make_float2(Bv.x, Bv.y);
                    float2 Bo = make_float2(Bv.z, Bv.w);
                    mma8(J[f], (const uint32_t*)&A0, (const uint32_t*)&Be);
                    mma8(J[f], (const uint32_t*)&A1, (const uint32_t*)&Bo);
                }
            }

            // ---- epilogue for this half ----
            {
                float* ob = out + (size_t)(4 * p + bq) * 4096;
                const int r0 = h2 * 32 + mq * 16 + g;
                #pragma unroll
                for (int f = 0; f < 4; f++){
                    const int cc = (nh * 4 + f) * 8 + 2 * tg;
                    *(float2*)(ob + (size_t)r0 * 64 + cc)       = make_float2(J[f][0], J[f][1]);
                    *(float2*)(ob + (size_t)(r0 + 8) * 64 + cc) = make_float2(J[f][2], J[f][3]);
                }
            }
            __syncthreads();   // half-image reads done; next half may repark
        }
    }
}

extern "C" void kernel_launch(void* const* d_in, const int* in_sizes, int n_in,
                              void* d_out, int out_size)
{
    const float* x  = (const float*)d_in[0];
    const float* W1 = (const float*)d_in[1];
    const float* b1 = (const float*)d_in[2];
    const float* W2 = (const float*)d_in[3];
    const float* b2 = (const float*)d_in[4];
    const float* W3 = (const float*)d_in[5];
    float* out = (float*)d_out;

    cudaFuncSetAttribute(setup, cudaFuncAttributeMaxDynamicSharedMemorySize, (64*66 + 256*66) * 4);
    cudaFuncSetAttribute(jmain, cudaFuncAttributeMaxDynamicSharedMemorySize, SMF * 4);

    setup<<<128, 256, (64*66 + 256*66) * 4>>>(x, W1, b1, W2, b2, W3);
    jmain<<<GRID_C, 512, SMF * 4>>>(out);
}

// round 16
// speedup vs baseline: 1.5209x; 1.1768x over previous
#include <cuda_runtime.h>
#include <cstdint>

#define GRID_C 148

__device__ float G1d[2097152]; // [8192][256] = 1 - h1^2
__device__ float G2d[2097152]; // [8192][256] = 1 - h2^2
__device__ float W2P[65536];   // frag-permuted tf32 W2, ks-paired: [tt32][ksg16][lane][4]
__device__ float W1P[16384];   // frag-permuted tf32 W1, ks-paired: [jt8][ksg16][lane][4]
__device__ float W3P[16384];   // frag-permuted tf32 W3^T (A-side): [mt4][ks32][lane][4]

typedef unsigned long long u64;
__device__ __forceinline__ float rnaf(float f){
    uint32_t o; asm("cvt.rna.tf32.f32 %0, %1;" : "=r"(o) : "f"(f)); return __uint_as_float(o);
}
__device__ __forceinline__ u64 pk2(float s){ u64 r; asm("mov.b64 %0,{%1,%1};" : "=l"(r) : "f"(s)); return r; }
__device__ __forceinline__ u64 fma2(u64 a, u64 b, u64 c){ u64 d; asm("fma.rn.f32x2 %0,%1,%2,%3;" : "=l"(d) : "l"(a), "l"(b), "l"(c)); return d; }
__device__ __forceinline__ void mma8(float* c, const uint32_t* a, const uint32_t* b){
    asm volatile("mma.sync.aligned.m16n8k8.row.col.f32.tf32.tf32.f32 "
        "{%0,%1,%2,%3},{%4,%5,%6,%7},{%8,%9},{%0,%1,%2,%3};"
        : "+f"(c[0]), "+f"(c[1]), "+f"(c[2]), "+f"(c[3])
        : "r"(a[0]), "r"(a[1]), "r"(a[2]), "r"(a[3]), "r"(b[0]), "r"(b[1]));
}
#define CPA(dst, src) asm volatile("cp.async.cg.shared.global [%0],[%1],16;" :: "r"(dst), "l"(src) : "memory")
__device__ __forceinline__ uint32_t su32(const void* p){
    uint32_t a; asm("{.reg .u64 t; cvta.to.shared.u64 t,%1; cvt.u32.u64 %0,t;}" : "=r"(a) : "l"(p)); return a;
}

// ---------------- setup: prep (weight images) + fwd (exact g1/g2), one launch ----------------
__global__ void __launch_bounds__(256, 1) setup(const float* __restrict__ x,  const float* __restrict__ W1,
                                                const float* __restrict__ b1, const float* __restrict__ W2,
                                                const float* __restrict__ b2, const float* __restrict__ W3){
    {
        int i = blockIdx.x * blockDim.x + threadIdx.x, stride = gridDim.x * blockDim.x;
        for (int idx = i; idx < 65536; idx += stride){
            int w = idx & 3, lane = (idx >> 2) & 31, ksg = (idx >> 7) & 15, tt = idx >> 11;
            int ks = 2 * ksg + (w >> 1), reg = w & 1;
            int l = tt * 8 + (lane >> 2), k = ks * 8 + (lane & 3) + 4 * reg;
            W2P[idx] = rnaf(W2[l * 256 + k]);
        }
        for (int idx = i; idx < 16384; idx += stride){
            int w = idx & 3, lane = (idx >> 2) & 31, ksg = (idx >> 7) & 15, jt = idx >> 11;
            int ks = 2 * ksg + (w >> 1), reg = w & 1;
            int j = jt * 8 + (lane >> 2), ll = ks * 8 + (lane & 3) + 4 * reg;
            W1P[idx] = rnaf(W1[j * 256 + ll]);
        }
        for (int idx = i; idx < 16384; idx += stride){
            int w = idx & 3, lane = (idx >> 2) & 31, ks = (idx >> 7) & 31, mt = idx >> 12;
            int m = mt * 16 + (lane >> 2) + 8 * (w & 1);
            int k = ks * 8 + (lane & 3) + 4 * (w >> 1);
            W3P[idx] = rnaf(W3[k * 64 + m]);
        }
    }
    extern __shared__ float fs[];
    float* xs  = fs;             // [64 j][66]
    float* h1t = fs + 64 * 66;   // [256 l][66]
    const int t = threadIdx.x;
    const int b0 = blockIdx.x * 64;
    for (int r = 0; r < 16; r++){
        int idx = r * 256 + t, b = idx >> 6, j = idx & 63;
        xs[j * 66 + b] = x[(size_t)(b0 + b) * 64 + j];
    }
    __syncthreads();
    u64 acc[32];
    #pragma unroll
    for (int q = 0; q < 32; q++) acc[q] = 0ull;
    for (int j = 0; j < 64; j++){
        u64 wp = pk2(W1[j * 256 + t]);
        const u64* xr = (const u64*)(xs + j * 66);
        #pragma unroll
        for (int q = 0; q < 32; q++) acc[q] = fma2(xr[q], wp, acc[q]);
    }
    float bb = b1[t];
    #pragma unroll
    for (int q = 0; q < 32; q++){
        float2 f; asm("mov.b64 {%0,%1},%2;" : "=f"(f.x), "=f"(f.y) : "l"(acc[q]));
        float ha = tanhf(f.x + bb), hb = tanhf(f.y + bb);
        h1t[t * 66 + 2*q] = ha; h1t[t * 66 + 2*q + 1] = hb;
        G1d[(size_t)(b0 + 2*q) * 256 + t]     = 1.f - ha * ha;
        G1d[(size_t)(b0 + 2*q + 1) * 256 + t] = 1.f - hb * hb;
    }
    __syncthreads();
    #pragma unroll
    for (int q = 0; q < 32; q++) acc[q] = 0ull;
    for (int l = 0; l < 256; l++){
        u64 wp = pk2(W2[l * 256 + t]);
        const u64* hr = (const u64*)(h1t + l * 66);
        #pragma unroll
        for (int q = 0; q < 32; q++) acc[q] = fma2(hr[q], wp, acc[q]);
    }
    bb = b2[t];
    #pragma unroll
    for (int q = 0; q < 32; q++){
        float2 f; asm("mov.b64 {%0,%1},%2;" : "=f"(f.x), "=f"(f.y) : "l"(acc[q]));
        float ha = tanhf(f.x + bb), hb = tanhf(f.y + bb);
        G2d[(size_t)(b0 + 2*q) * 256 + t]     = 1.f - ha * ha;
        G2d[(size_t)(b0 + 2*q + 1) * 256 + t] = 1.f - hb * hb;
    }
}

// ---------------- jmain: 256 thr (8 warps x 255 regs), 4 batches/CTA, m32n32 tiles ----------------
// smem floats: W3s 16384 | C1H 4x8192 | g2q 2x1024(parity)
#define SMF (16384 + 32768 + 2048)

__global__ void __launch_bounds__(256, 1) jmain(float* __restrict__ out){
    extern __shared__ float s[];
    float* W3s = s;                 // 16384
    float* C1H = s + 16384;         // 4 x 8192 (per-batch m32-half A2 image)
    float* g2q = C1H + 32768;       // 2 x 1024 (parity float4 quads)

    const int t = threadIdx.x, lane = t & 31, wid = t >> 5;   // wid 0..7
    const int g = lane >> 2, tg = lane & 3;
    const uint32_t w3sb = su32(W3s);

    // resident W3P (A operand), loaded once
    #pragma unroll
    for (int i = 0; i < 16; i++){
        int u = t + i * 256;
        CPA(w3sb + (uint32_t)u * 16, (const char*)W3P + u * 16);
    }
    asm volatile("cp.async.commit_group;\ncp.async.wait_group 0;" ::: "memory");
    __syncthreads();

    const float4* W3s4 = (const float4*)W3s;
    const float4* B1p  = (const float4*)W2P;
    const float4* B2p  = (const float4*)W1P;
    const float4* g2q4 = (const float4*)g2q;

    // GEMM2 warp map: batch bq, n32 half nh
    const int bq = wid & 3, nh = wid >> 2;
    const float4* A2b4 = (const float4*)(C1H + bq * 8192);
    const int idxA = tg * 8 + g;

    // park constants
    const int ca = (2 * tg) & 3, wa = 2 * ((2 * tg) >> 2);
    const int cb = (2 * tg + 1) & 3;

    int it = 0;
    for (int p = blockIdx.x; p < 2048; p += GRID_C, it ^= 1){
        // build g2 float4 quads for 4 batches
        {
            const int b = t >> 6, e = t & 63;
            const size_t base = (size_t)(4 * p + b) * 256 + 16 * (e >> 2) + (e & 3);
            float4 v;
            v.x = G2d[base]; v.y = G2d[base + 4]; v.z = G2d[base + 8]; v.w = G2d[base + 12];
            ((float4*)g2q)[it * 256 + t] = v;
        }
        __syncthreads();

        #pragma unroll 1
        for (int h2 = 0; h2 < 2; h2++){
            // ---- GEMM1: warp tile m32 x n32 x 4 batches, this m-half ----
            float C1r[4][2][4][4];   // [b][ml][f][q] -- 128 regs
            #pragma unroll
            for (int b = 0; b < 4; b++)
                #pragma unroll
                for (int ml = 0; ml < 2; ml++)
                    #pragma unroll
                    for (int f = 0; f < 4; f++)
                        #pragma unroll
                        for (int q = 0; q < 4; q++) C1r[b][ml][f][q] = 0.f;

            #pragma unroll 2
            for (int ksg = 0; ksg < 16; ksg++){
                float4 Ae0 = W3s4[((2 * h2 + 0) * 32 + 2 * ksg)     * 32 + lane];
                float4 Ao0 = W3s4[((2 * h2 + 0) * 32 + 2 * ksg + 1) * 32 + lane];
                float4 Ae1 = W3s4[((2 * h2 + 1) * 32 + 2 * ksg)     * 32 + lane];
                float4 Ao1 = W3s4[((2 * h2 + 1) * 32 + 2 * ksg + 1) * 32 + lane];
                float4 Bf[4];
                #pragma unroll
                for (int f = 0; f < 4; f++)
                    Bf[f] = B1p[((4 * wid + f) * 16 + ksg) * 32 + lane];
                float4 gq[4];
                #pragma unroll
                for (int b = 0; b < 4; b++)
                    gq[b] = g2q4[it * 256 + b * 64 + ksg * 4 + tg];
                #pragma unroll
                for (int b = 0; b < 4; b++){
                    #pragma unroll
                    for (int f = 0; f < 4; f++){
                        float2 Se, So;
                        Se.x = rnaf(Bf[f].x * gq[b].x); Se.y = rnaf(Bf[f].y * gq[b].y);
                        So.x = rnaf(Bf[f].z * gq[b].z); So.y = rnaf(Bf[f].w * gq[b].w);
                        mma8(C1r[b][0][f], (const uint32_t*)&Ae0, (const uint32_t*)&Se);
                        mma8(C1r[b][0][f], (const uint32_t*)&Ao0, (const uint32_t*)&So);
                        mma8(C1r[b][1][f], (const uint32_t*)&Ae1, (const uint32_t*)&Se);
                        mma8(C1r[b][1][f], (const uint32_t*)&Ao1, (const uint32_t*)&So);
                    }
                }
            }

            // ---- park: scale by g1, frag-permuted half-images ----
            #pragma unroll
            for (int b = 0; b < 4; b++){
                float* C1w = C1H + b * 8192;
                const float* g1b = G1d + (size_t)(4 * p + b) * 256;
                #pragma unroll
                for (int f = 0; f < 4; f++){
                    const int ss = 4 * wid + f;
                    const float gv0 = __ldg(g1b + ss * 8 + 2 * tg);
                    const float gv1 = __ldg(g1b + ss * 8 + 2 * tg + 1);
                    #pragma unroll
                    for (int ml = 0; ml < 2; ml++){
                        float2 v0, v1;
                        v0.x = rnaf(C1r[b][ml][f][0] * gv0); v0.y = rnaf(C1r[b][ml][f][2] * gv0);
                        v1.x = rnaf(C1r[b][ml][f][1] * gv1); v1.y = rnaf(C1r[b][ml][f][3] * gv1);
                        *(float2*)&C1w[((ml * 32 + ss) * 32 + ca * 8 + g) * 4 + wa] = v0;
                        *(float2*)&C1w[((ml * 32 + ss) * 32 + cb * 8 + g) * 4 + wa] = v1;
                    }
                }
            }
            __syncthreads();   // half-images complete

            // ---- GEMM2 on this m-half: warp tile m32 x n32 ----
            float J[2][4][4];   // [ml][f]
            #pragma unroll
            for (int ml = 0; ml < 2; ml++)
                #pragma unroll
                for (int f = 0; f < 4; f++)
                    #pragma unroll
                    for (int q = 0; q < 4; q++) J[ml][f][q] = 0.f;

            #pragma unroll 2
            for (int ksg = 0; ksg < 16; ksg++){
                float4 Ae0 = A2b4[( 0 + 2 * ksg)     * 32 + idxA];
                float4 Ao0 = A2b4[( 0 + 2 * ksg + 1) * 32 + idxA];
                float4 Ae1 = A2b4[(32 + 2 * ksg)     * 32 + idxA];
                float4 Ao1 = A2b4[(32 + 2 * ksg + 1) * 32 + idxA];
                #pragma unroll
                for (int f = 0; f < 4; f++){
                    float4 Bv = B2p[((nh * 4 + f) * 16 + ksg) * 32 + lane];
                    float2 Be = make_float2(Bv.x, Bv.y);
                    float2 Bo = make_float2(Bv.z, Bv.w);
                    mma8(J[0][f], (const uint32_t*)&Ae0, (const uint32_t*)&Be);
                    mma8(J[0][f], (const uint32_t*)&Ao0, (const uint32_t*)&Bo);
                    mma8(J[1][f], (const uint32_t*)&Ae1, (const uint32_t*)&Be);
                    mma8(J[1][f], (const uint32_t*)&Ao1, (const uint32_t*)&Bo);
                }
            }

            // ---- epilogue for this half ----
            {
                float* ob = out + (size_t)(4 * p + bq) * 4096;
                #pragma unroll
                for (int ml = 0; ml < 2; ml++){
                    const int r0 = h2 * 32 + ml * 16 + g;
                    #pragma unroll
                    for (int f = 0; f < 4; f++){
                        const int cc = (nh * 4 + f) * 8 + 2 * tg;
                        *(float2*)(ob + (size_t)r0 * 64 + cc)       = make_float2(J[ml][f][0], J[ml][f][1]);
                        *(float2*)(ob + (size_t)(r0 + 8) * 64 + cc) = make_float2(J[ml][f][2], J[ml][f][3]);
                    }
                }
            }
            __syncthreads();   // half-image reads done; next half may repark
        }
    }
}

extern "C" void kernel_launch(void* const* d_in, const int* in_sizes, int n_in,
                              void* d_out, int out_size)
{
    const float* x  = (const float*)d_in[0];
    const float* W1 = (const float*)d_in[1];
    const float* b1 = (const float*)d_in[2];
    const float* W2 = (const float*)d_in[3];
    const float* b2 = (const float*)d_in[4];
    const float* W3 = (const float*)d_in[5];
    float* out = (float*)d_out;

    cudaFuncSetAttribute(setup, cudaFuncAttributeMaxDynamicSharedMemorySize, (64*66 + 256*66) * 4);
    cudaFuncSetAttribute(jmain, cudaFuncAttributeMaxDynamicSharedMemorySize, SMF * 4);

    setup<<<128, 256, (64*66 + 256*66) * 4>>>(x, W1, b1, W2, b2, W3);
    jmain<<<GRID_C, 256, SMF * 4>>>(out);
}